// round 5
// baseline (speedup 1.0000x reference)
#include <cuda_runtime.h>
#include <math.h>

// MultiHeadedAttention_11562051961106
// B=2, S=4096, D=512, H=8, DK=64. fp32 in/out. Causal (mask input ignored).
//
// Stage 1: q/k/v = x @ W^T + b    (tiled FFMA2 GEMMs, epilogue -> [B,H,S,DK])
// Stage 2: causal flash attention, R5:
//          - 256 threads/CTA (4 warps/SMSP at 2 CTAs/SM)
//          - softmax fully in registers via __shfl_xor (no score round-trip)
//          - P staged with XOR bank swizzle (conflict-free stores + aligned reads)
// Stage 3: out = attn @ Wo^T + bo

#define B_  2
#define S_  4096
#define D_  512
#define H_  8
#define DK_ 64
#define M_  (B_*S_)

typedef unsigned long long u64;

// ---- packed f32x2 helpers (Blackwell sm_10x) -------------------------------
__device__ __forceinline__ u64 pack2(float lo, float hi) {
    u64 d;
    asm("mov.b64 %0, {%1, %2};" : "=l"(d) : "f"(lo), "f"(hi));
    return d;
}
__device__ __forceinline__ void unpack2(u64 v, float& lo, float& hi) {
    asm("mov.b64 {%0, %1}, %2;" : "=f"(lo), "=f"(hi) : "l"(v));
}
__device__ __forceinline__ u64 fma2(u64 a, u64 b, u64 c) {
    u64 d;
    asm("fma.rn.f32x2 %0, %1, %2, %3;" : "=l"(d) : "l"(a), "l"(b), "l"(c));
    return d;
}
__device__ __forceinline__ u64 mul2(u64 a, u64 b) {
    u64 d;
    asm("mul.rn.f32x2 %0, %1, %2;" : "=l"(d) : "l"(a), "l"(b));
    return d;
}

// Scratch (device globals; no allocation allowed)
__device__ float g_q[(size_t)B_*H_*S_*DK_];
__device__ float g_k[(size_t)B_*H_*S_*DK_];
__device__ float g_v[(size_t)B_*H_*S_*DK_];
__device__ float g_attn[(size_t)M_*D_];

// ---------------------------------------------------------------------------
// GEMM: C = A @ W^T + bias (unchanged; FFMA2 core).
// ---------------------------------------------------------------------------
template<int MODE>
__global__ void __launch_bounds__(256) gemm_bias_kernel(
    const float* __restrict__ Ain, const float* __restrict__ W,
    const float* __restrict__ bias, float* __restrict__ outp)
{
    const float* A = (MODE == 3) ? g_attn : Ain;
    float* OUT;
    if      (MODE == 0) OUT = g_q;
    else if (MODE == 1) OUT = g_k;
    else if (MODE == 2) OUT = g_v;
    else                OUT = outp;

    __shared__ float As[16][68];
    __shared__ float Bs[16][68];

    const int tid = threadIdx.x;
    const int tx  = tid & 15;
    const int ty  = tid >> 4;
    const int m0  = blockIdx.y * 64;
    const int n0  = blockIdx.x * 64;

    u64 acc2[2][4];
    #pragma unroll
    for (int ip = 0; ip < 2; ip++)
        #pragma unroll
        for (int j = 0; j < 4; j++) acc2[ip][j] = 0ull;

    for (int k0 = 0; k0 < D_; k0 += 16) {
        #pragma unroll
        for (int p = 0; p < 4; p++) {
            const int lm = ty + p*16;
            As[tx][lm] = A[(size_t)(m0 + lm)*D_ + k0 + tx];
            Bs[tx][lm] = W[(size_t)(n0 + lm)*D_ + k0 + tx];
        }
        __syncthreads();

        #pragma unroll
        for (int kk = 0; kk < 16; kk++) {
            const ulonglong2 a2 = *(const ulonglong2*)&As[kk][ty*4];
            const float4 b4 = *(const float4*)&Bs[kk][tx*4];
            const u64 bb[4] = { pack2(b4.x, b4.x), pack2(b4.y, b4.y),
                                pack2(b4.z, b4.z), pack2(b4.w, b4.w) };
            #pragma unroll
            for (int j = 0; j < 4; j++) {
                acc2[0][j] = fma2(a2.x, bb[j], acc2[0][j]);
                acc2[1][j] = fma2(a2.y, bb[j], acc2[1][j]);
            }
        }
        __syncthreads();
    }

    #pragma unroll
    for (int ip = 0; ip < 2; ip++) {
        #pragma unroll
        for (int j = 0; j < 4; j++) {
            float c0, c1;
            unpack2(acc2[ip][j], c0, c1);
            const int n = n0 + tx*4 + j;
            const float bz = bias[n];
            #pragma unroll
            for (int h = 0; h < 2; h++) {
                const int m = m0 + ty*4 + ip*2 + h;
                const float v = (h ? c1 : c0) + bz;
                if (MODE < 3) {
                    const int bb_ = m >> 12;
                    const int ss  = m & (S_ - 1);
                    const int hh  = n >> 6;
                    const int dk  = n & (DK_ - 1);
                    OUT[((size_t)((bb_*H_ + hh)*S_) + ss)*DK_ + dk] = v;
                } else {
                    OUT[(size_t)m*D_ + n] = v;
                }
            }
        }
    }
}

// ---------------------------------------------------------------------------
// R5 flash attention. Grid (B*H, S/128), block 256.
// Per block: 128 queries, key tiles of 32.
//
// SMEM (66560 B):
//   Qs [64][128]  Q^T pre-scaled
//   Ks [64][32]   K^T (conflict-free scatter: lane = key row)
//   Vs [32][68]   V padded
//   Ps [32][128]  P, XOR-swizzled: pair (q&~1,q|1) of row j lives at
//                 col = (q&~1) ^ ((j>>1)<<1)   (conflict-free u64 stores,
//                 aligned float4 reads with compile-time component swap)
//   Cs [128]      per-row rescale factor / final 1/l
//
// QK mapping: qg=t>>4 (8q), kg=t&15 (2k). Softmax: shuffle-reduce over the
// 16 kg lanes (lane bits 0-3), all state in registers.
// PV mapping: qg2=t>>3 (4q), dg=t&7 (8d); o accumulated packed by d-pair.
// ---------------------------------------------------------------------------
#define FLASH_SMEM_FLOATS 16640

__global__ void __launch_bounds__(256, 2) flash_kernel()
{
    extern __shared__ float sm[];
    float* Qs = sm;            // [64][128]
    float* Ks = sm + 8192;     // [64][32]
    float* Vs = sm + 10240;    // [32][68]
    float* Ps = sm + 12416;    // [32][128]
    float* Cs = sm + 16512;    // [128]

    const int bh = blockIdx.x;                   // 0..15
    const int qt = gridDim.y - 1 - blockIdx.y;   // heavy-first
    const int q0 = qt * 128;
    const int t  = threadIdx.x;

    const int qg  = t >> 4;      // QK: 0..15 (8 queries)
    const int kg  = t & 15;      // QK: 0..15 (2 keys)
    const int qg2 = t >> 3;      // PV: 0..31 (4 queries)
    const int dg  = t & 7;       // PV: 0..7  (8 dims)
    const int jl  = t & 31;      // staging: key row
    const int dh  = t >> 5;      // staging: warp id 0..7 (8-dim chunk)

    // ---- load Q tile transposed + pre-scaled (once) ----
    {
        const int qc   = t & 127;
        const int half = t >> 7;
        const float4* src = (const float4*)(g_q + ((size_t)bh*S_ + q0 + qc)*DK_);
        #pragma unroll
        for (int cc = 0; cc < 8; cc++) {
            const int c = half*8 + cc;
            const float4 f = src[c];
            Qs[(4*c+0)*128 + qc] = f.x*0.125f;
            Qs[(4*c+1)*128 + qc] = f.y*0.125f;
            Qs[(4*c+2)*128 + qc] = f.z*0.125f;
            Qs[(4*c+3)*128 + qc] = f.w*0.125f;
        }
    }

    float m_[8], l_[8];
    #pragma unroll
    for (int i = 0; i < 8; i++) { m_[i] = -1e30f; l_[i] = 0.f; }

    u64 o2[4][4];   // [4 queries][4 d-pairs]
    #pragma unroll
    for (int i = 0; i < 4; i++)
        #pragma unroll
        for (int j = 0; j < 4; j++) o2[i][j] = 0ull;

    const float* kbase = g_k + (size_t)bh*S_*DK_;
    const float* vbase = g_v + (size_t)bh*S_*DK_;
    const int kend = q0 + 128;

    for (int j0 = 0; j0 < kend; j0 += 32) {
        __syncthreads();   // prev tile's PV reads done

        // ---- stage K^T (conflict-free scatter) + V (padded) ----
        {
            const float4* krow = (const float4*)(kbase + (size_t)(j0 + jl)*DK_) + dh*2;
            const float4* vrow = (const float4*)(vbase + (size_t)(j0 + jl)*DK_) + dh*2;
            #pragma unroll
            for (int c = 0; c < 2; c++) {
                const float4 f = krow[c];
                const int d = dh*8 + 4*c;
                Ks[(d+0)*32 + jl] = f.x;
                Ks[(d+1)*32 + jl] = f.y;
                Ks[(d+2)*32 + jl] = f.z;
                Ks[(d+3)*32 + jl] = f.w;
                *(float4*)&Vs[jl*68 + d] = vrow[c];
            }
        }
        __syncthreads();   // tiles ready

        // ---- QK: 8q x 2k per thread ----
        u64 acc[4][2];
        #pragma unroll
        for (int p = 0; p < 4; p++) { acc[p][0] = 0ull; acc[p][1] = 0ull; }

        #pragma unroll 16
        for (int d = 0; d < DK_; d++) {
            const ulonglong2 qa = *(const ulonglong2*)&Qs[d*128 + qg*8];
            const ulonglong2 qb = *(const ulonglong2*)&Qs[d*128 + qg*8 + 4];
            const float2 kv = *(const float2*)&Ks[d*32 + kg*2];
            const u64 k0 = pack2(kv.x, kv.x);
            const u64 k1 = pack2(kv.y, kv.y);
            const u64 qp[4] = { qa.x, qa.y, qb.x, qb.y };
            #pragma unroll
            for (int p = 0; p < 4; p++) {
                acc[p][0] = fma2(qp[p], k0, acc[p][0]);
                acc[p][1] = fma2(qp[p], k1, acc[p][1]);
            }
        }

        // ---- softmax in registers (shuffle over the 16 kg lanes) ----
        float sf[8][2];
        #pragma unroll
        for (int p = 0; p < 4; p++) {
            unpack2(acc[p][0], sf[2*p][0], sf[2*p+1][0]);
            unpack2(acc[p][1], sf[2*p][1], sf[2*p+1][1]);
        }

        if (j0 >= q0) {                        // diagonal tiles: causal mask
            const int qb = q0 + qg*8;
            const int jb = j0 + kg*2;
            #pragma unroll
            for (int i = 0; i < 8; i++) {
                if (jb     > qb + i) sf[i][0] = -1e30f;
                if (jb + 1 > qb + i) sf[i][1] = -1e30f;
            }
        }

        float mx8[8];
        #pragma unroll
        for (int i = 0; i < 8; i++) mx8[i] = fmaxf(sf[i][0], sf[i][1]);
        #pragma unroll
        for (int off = 1; off < 16; off <<= 1)
            #pragma unroll
            for (int i = 0; i < 8; i++)
                mx8[i] = fmaxf(mx8[i], __shfl_xor_sync(0xFFFFFFFFu, mx8[i], off));

        float cf[8];
        #pragma unroll
        for (int i = 0; i < 8; i++) {
            const float mn = fmaxf(m_[i], mx8[i]);
            cf[i] = __expf(m_[i] - mn);
            m_[i] = mn;
        }

        float ls[8];
        #pragma unroll
        for (int i = 0; i < 8; i++) {
            sf[i][0] = __expf(sf[i][0] - m_[i]);
            sf[i][1] = __expf(sf[i][1] - m_[i]);
            ls[i] = sf[i][0] + sf[i][1];
        }
        #pragma unroll
        for (int off = 1; off < 16; off <<= 1)
            #pragma unroll
            for (int i = 0; i < 8; i++)
                ls[i] += __shfl_xor_sync(0xFFFFFFFFu, ls[i], off);
        #pragma unroll
        for (int i = 0; i < 8; i++) l_[i] = l_[i]*cf[i] + ls[i];

        if (kg < 8) Cs[qg*8 + kg] = cf[kg];    // all kg lanes hold identical cf[]

        // ---- store P swizzled (conflict-free u64 stores) ----
        #pragma unroll
        for (int k = 0; k < 2; k++) {
            const int j = kg*2 + k;
            #pragma unroll
            for (int p = 0; p < 4; p++) {
                const int col = (qg*8 + 2*p) ^ (kg << 1);
                *(u64*)&Ps[j*128 + col] = pack2(sf[2*p][k], sf[2*p+1][k]);
            }
        }
        __syncthreads();   // Ps, Cs ready

        // ---- PV: 4q x 8d per thread, accumulate in regs ----
        #pragma unroll
        for (int i = 0; i < 4; i++) {
            const float cv = Cs[qg2*4 + i];
            const u64 c2 = pack2(cv, cv);
            #pragma unroll
            for (int dp = 0; dp < 4; dp++) o2[i][dp] = mul2(o2[i][dp], c2);
        }
        #pragma unroll
        for (int j = 0; j < 32; j++) {
            const int base = (qg2*4) ^ ((j >> 2) << 2);
            const float4 f = *(const float4*)&Ps[j*128 + base];
            // component swap when bit1 of the swizzle is set
            float p0, p1, p2, p3;
            if ((j >> 1) & 1) { p0 = f.z; p1 = f.w; p2 = f.x; p3 = f.y; }
            else              { p0 = f.x; p1 = f.y; p2 = f.z; p3 = f.w; }
            const ulonglong2 va = *(const ulonglong2*)&Vs[j*68 + dg*8];
            const ulonglong2 vb = *(const ulonglong2*)&Vs[j*68 + dg*8 + 4];
            const u64 pd[4] = { pack2(p0,p0), pack2(p1,p1),
                                pack2(p2,p2), pack2(p3,p3) };
            const u64 vp[4] = { va.x, va.y, vb.x, vb.y };
            #pragma unroll
            for (int i = 0; i < 4; i++)
                #pragma unroll
                for (int dp = 0; dp < 4; dp++)
                    o2[i][dp] = fma2(pd[i], vp[dp], o2[i][dp]);
        }
    }

    // ---- epilogue: broadcast 1/l, scale, write [B,S,H*DK] ----
    __syncthreads();
    if (kg < 8) Cs[qg*8 + kg] = 1.0f / l_[kg];
    __syncthreads();

    const int bb = bh >> 3;
    const int hh = bh & 7;
    #pragma unroll
    for (int i = 0; i < 4; i++) {
        const float inv = Cs[qg2*4 + i];
        const int qo = q0 + qg2*4 + i;
        float* orow = g_attn + ((size_t)(bb*S_ + qo))*D_ + hh*DK_ + dg*8;
        float r[8];
        #pragma unroll
        for (int dp = 0; dp < 4; dp++) unpack2(o2[i][dp], r[2*dp], r[2*dp+1]);
        float4 t0, t1;
        t0.x = r[0]*inv; t0.y = r[1]*inv; t0.z = r[2]*inv; t0.w = r[3]*inv;
        t1.x = r[4]*inv; t1.y = r[5]*inv; t1.z = r[6]*inv; t1.w = r[7]*inv;
        *(float4*)orow       = t0;
        *(float4*)(orow + 4) = t1;
    }
}

// ---------------------------------------------------------------------------
// Inputs: query, key, value, Wq, bq, Wk, bk, Wv, bv, Wo, bo, mask
// ---------------------------------------------------------------------------
extern "C" void kernel_launch(void* const* d_in, const int* in_sizes, int n_in,
                              void* d_out, int out_size)
{
    const float* query = (const float*)d_in[0];
    const float* key   = (const float*)d_in[1];
    const float* value = (const float*)d_in[2];
    const float* Wq    = (const float*)d_in[3];
    const float* bq    = (const float*)d_in[4];
    const float* Wk    = (const float*)d_in[5];
    const float* bk    = (const float*)d_in[6];
    const float* Wv    = (const float*)d_in[7];
    const float* bv    = (const float*)d_in[8];
    const float* Wo    = (const float*)d_in[9];
    const float* bo    = (const float*)d_in[10];
    float* out = (float*)d_out;

    const dim3 gthr(256);
    const dim3 ggrid(D_/64, M_/64);   // (8, 128)

    gemm_bias_kernel<0><<<ggrid, gthr>>>(query, Wq, bq, nullptr);
    gemm_bias_kernel<1><<<ggrid, gthr>>>(key,   Wk, bk, nullptr);
    gemm_bias_kernel<2><<<ggrid, gthr>>>(value, Wv, bv, nullptr);

    const size_t fsm = FLASH_SMEM_FLOATS * sizeof(float);   // 66560 B
    cudaFuncSetAttribute(flash_kernel,
                         cudaFuncAttributeMaxDynamicSharedMemorySize, (int)fsm);
    const dim3 fgrid(B_*H_, S_/128);  // (16, 32)
    flash_kernel<<<fgrid, 256, fsm>>>();

    gemm_bias_kernel<3><<<ggrid, gthr>>>(nullptr, Wo, bo, out);
}

// round 7
// speedup vs baseline: 1.1932x; 1.1932x over previous
#include <cuda_runtime.h>
#include <math.h>

// MultiHeadedAttention_11562051961106
// B=2, S=4096, D=512, H=8, DK=64. fp32 in/out. Causal (mask input ignored).
//
// Stage 1: q/k/v = x @ W^T + b    (tiled FFMA2 GEMMs, epilogue -> [B,H,S,DK])
// Stage 2: causal flash attention, R6b = R4 tiling (128 thr, 8qx4k / 8qx8d)
//          + register softmax (shfl over the 8 kg lanes; Ss deleted)
//          + conflict-free XOR-swizzled P staging:
//              col = q ^ ((j>>2)<<1) ^ ((j>>4)<<4)
//            (u64 stores injective per 16-lane phase -> 2-wf floor)
// Stage 3: out = attn @ Wo^T + bo

#define B_  2
#define S_  4096
#define D_  512
#define H_  8
#define DK_ 64
#define M_  (B_*S_)

typedef unsigned long long u64;

// ---- packed f32x2 helpers (Blackwell sm_10x) -------------------------------
__device__ __forceinline__ u64 pack2(float lo, float hi) {
    u64 d;
    asm("mov.b64 %0, {%1, %2};" : "=l"(d) : "f"(lo), "f"(hi));
    return d;
}
__device__ __forceinline__ void unpack2(u64 v, float& lo, float& hi) {
    asm("mov.b64 {%0, %1}, %2;" : "=f"(lo), "=f"(hi) : "l"(v));
}
__device__ __forceinline__ u64 fma2(u64 a, u64 b, u64 c) {
    u64 d;
    asm("fma.rn.f32x2 %0, %1, %2, %3;" : "=l"(d) : "l"(a), "l"(b), "l"(c));
    return d;
}
__device__ __forceinline__ u64 mul2(u64 a, u64 b) {
    u64 d;
    asm("mul.rn.f32x2 %0, %1, %2;" : "=l"(d) : "l"(a), "l"(b));
    return d;
}

// Scratch (device globals; no allocation allowed)
__device__ float g_q[(size_t)B_*H_*S_*DK_];
__device__ float g_k[(size_t)B_*H_*S_*DK_];
__device__ float g_v[(size_t)B_*H_*S_*DK_];
__device__ float g_attn[(size_t)M_*D_];

// ---------------------------------------------------------------------------
// GEMM: C = A @ W^T + bias (unchanged; FFMA2 core).
// ---------------------------------------------------------------------------
template<int MODE>
__global__ void __launch_bounds__(256) gemm_bias_kernel(
    const float* __restrict__ Ain, const float* __restrict__ W,
    const float* __restrict__ bias, float* __restrict__ outp)
{
    const float* A = (MODE == 3) ? g_attn : Ain;
    float* OUT;
    if      (MODE == 0) OUT = g_q;
    else if (MODE == 1) OUT = g_k;
    else if (MODE == 2) OUT = g_v;
    else                OUT = outp;

    __shared__ float As[16][68];
    __shared__ float Bs[16][68];

    const int tid = threadIdx.x;
    const int tx  = tid & 15;
    const int ty  = tid >> 4;
    const int m0  = blockIdx.y * 64;
    const int n0  = blockIdx.x * 64;

    u64 acc2[2][4];
    #pragma unroll
    for (int ip = 0; ip < 2; ip++)
        #pragma unroll
        for (int j = 0; j < 4; j++) acc2[ip][j] = 0ull;

    for (int k0 = 0; k0 < D_; k0 += 16) {
        #pragma unroll
        for (int p = 0; p < 4; p++) {
            const int lm = ty + p*16;
            As[tx][lm] = A[(size_t)(m0 + lm)*D_ + k0 + tx];
            Bs[tx][lm] = W[(size_t)(n0 + lm)*D_ + k0 + tx];
        }
        __syncthreads();

        #pragma unroll
        for (int kk = 0; kk < 16; kk++) {
            const ulonglong2 a2 = *(const ulonglong2*)&As[kk][ty*4];
            const float4 b4 = *(const float4*)&Bs[kk][tx*4];
            const u64 bb[4] = { pack2(b4.x, b4.x), pack2(b4.y, b4.y),
                                pack2(b4.z, b4.z), pack2(b4.w, b4.w) };
            #pragma unroll
            for (int j = 0; j < 4; j++) {
                acc2[0][j] = fma2(a2.x, bb[j], acc2[0][j]);
                acc2[1][j] = fma2(a2.y, bb[j], acc2[1][j]);
            }
        }
        __syncthreads();
    }

    #pragma unroll
    for (int ip = 0; ip < 2; ip++) {
        #pragma unroll
        for (int j = 0; j < 4; j++) {
            float c0, c1;
            unpack2(acc2[ip][j], c0, c1);
            const int n = n0 + tx*4 + j;
            const float bz = bias[n];
            #pragma unroll
            for (int h = 0; h < 2; h++) {
                const int m = m0 + ty*4 + ip*2 + h;
                const float v = (h ? c1 : c0) + bz;
                if (MODE < 3) {
                    const int bb_ = m >> 12;
                    const int ss  = m & (S_ - 1);
                    const int hh  = n >> 6;
                    const int dk  = n & (DK_ - 1);
                    OUT[((size_t)((bb_*H_ + hh)*S_) + ss)*DK_ + dk] = v;
                } else {
                    OUT[(size_t)m*D_ + n] = v;
                }
            }
        }
    }
}

// ---------------------------------------------------------------------------
// R6b flash attention. Grid (B*H, S/128), block 128.
// Per block: 128 queries, key tiles of 32.
//
// SMEM (66560 B):
//   Qs [64][128]  Q^T pre-scaled
//   Ks [64][32]   K^T (conflict-free scatter: lane = key row)
//   Vs [32][68]   V padded
//   Ps [32][128]  P, swizzled: P[q][j] at col = q ^ ((j>>2)<<1) ^ ((j>>4)<<4)
//   Cs [128]      per-row rescale factor / final 1/l
//
// Mapping (both phases): qg = t>>3 (8 q rows), kg = t&7 (4 keys / 8 dims).
// Softmax: thread group (qg, kg=0..7) owns rows qg*8..+7; row reductions are
// 3-step __shfl_xor over kg lanes; m/l state fully in registers.
// ---------------------------------------------------------------------------
#define FLASH_SMEM_FLOATS 16640

__global__ void __launch_bounds__(128, 2) flash_kernel()
{
    extern __shared__ float sm[];
    float* Qs = sm;            // [64][128]
    float* Ks = sm + 8192;     // [64][32]
    float* Vs = sm + 10240;    // [32][68]
    float* Ps = sm + 12416;    // [32][128]
    float* Cs = sm + 16512;    // [128]

    const int bh = blockIdx.x;                   // 0..15
    const int qt = gridDim.y - 1 - blockIdx.y;   // heavy-first
    const int q0 = qt * 128;
    const int t  = threadIdx.x;
    const int qg = t >> 3;                       // 0..15 (8-query group)
    const int kg = t & 7;                        // 0..7  (4-key / 8-dim group)

    // ---- load Q tile transposed + pre-scaled (once) ----
    {
        const float4* src = (const float4*)(g_q + ((size_t)bh*S_ + q0 + t)*DK_);
        #pragma unroll
        for (int c = 0; c < 16; c++) {
            const float4 f = src[c];
            Qs[(4*c+0)*128 + t] = f.x*0.125f;
            Qs[(4*c+1)*128 + t] = f.y*0.125f;
            Qs[(4*c+2)*128 + t] = f.z*0.125f;
            Qs[(4*c+3)*128 + t] = f.w*0.125f;
        }
    }

    float m_[8], l_[8];
    #pragma unroll
    for (int i = 0; i < 8; i++) { m_[i] = -1e30f; l_[i] = 0.f; }

    u64 o2[8][4];
    #pragma unroll
    for (int i = 0; i < 8; i++)
        #pragma unroll
        for (int j = 0; j < 4; j++) o2[i][j] = 0ull;

    const float* kbase = g_k + (size_t)bh*S_*DK_;
    const float* vbase = g_v + (size_t)bh*S_*DK_;
    const int jl = t & 31;            // staging: key row (= lane id)
    const int dh = t >> 5;            // staging: warp id (16-d chunk)
    const int kend = q0 + 128;

    for (int j0 = 0; j0 < kend; j0 += 32) {
        __syncthreads();   // prev tile's Ps/Vs reads done

        // ---- stage K^T (conflict-free scatter) + V (padded) ----
        {
            const float4* krow = (const float4*)(kbase + (size_t)(j0 + jl)*DK_ + dh*16);
            const float4* vrow = (const float4*)(vbase + (size_t)(j0 + jl)*DK_ + dh*16);
            #pragma unroll
            for (int c = 0; c < 4; c++) {
                const float4 f = krow[c];
                const int d = dh*16 + 4*c;
                Ks[(d+0)*32 + jl] = f.x;
                Ks[(d+1)*32 + jl] = f.y;
                Ks[(d+2)*32 + jl] = f.z;
                Ks[(d+3)*32 + jl] = f.w;
                *(float4*)&Vs[jl*68 + d] = vrow[c];
            }
        }
        __syncthreads();   // tiles ready

        // ---- QK: 8q x 4k per thread (keys kg*4..kg*4+3) ----
        u64 acc[4][4];
        #pragma unroll
        for (int p = 0; p < 4; p++)
            #pragma unroll
            for (int k = 0; k < 4; k++) acc[p][k] = 0ull;

        #pragma unroll 8
        for (int d = 0; d < DK_; d++) {
            const ulonglong2 qa = *(const ulonglong2*)&Qs[d*128 + qg*8];
            const ulonglong2 qb = *(const ulonglong2*)&Qs[d*128 + qg*8 + 4];
            const float4 kv = *(const float4*)&Ks[d*32 + kg*4];
            const u64 qp[4] = { qa.x, qa.y, qb.x, qb.y };
            const u64 kd[4] = { pack2(kv.x, kv.x), pack2(kv.y, kv.y),
                                pack2(kv.z, kv.z), pack2(kv.w, kv.w) };
            #pragma unroll
            for (int p = 0; p < 4; p++)
                #pragma unroll
                for (int k = 0; k < 4; k++)
                    acc[p][k] = fma2(qp[p], kd[k], acc[p][k]);
        }

        // ---- softmax in registers (shuffle over the 8 kg lanes) ----
        float sf[8][4];   // sf[i][k] = S[qg*8+i][kg*4+k]
        #pragma unroll
        for (int p = 0; p < 4; p++)
            #pragma unroll
            for (int k = 0; k < 4; k++)
                unpack2(acc[p][k], sf[2*p][k], sf[2*p+1][k]);

        if (j0 >= q0) {                          // diagonal tiles: causal mask
            const int qb = q0 + qg*8;
            const int jb = j0 + kg*4;
            #pragma unroll
            for (int i = 0; i < 8; i++)
                #pragma unroll
                for (int k = 0; k < 4; k++)
                    if (jb + k > qb + i) sf[i][k] = -1e30f;
        }

        float mx8[8];
        #pragma unroll
        for (int i = 0; i < 8; i++)
            mx8[i] = fmaxf(fmaxf(sf[i][0], sf[i][1]), fmaxf(sf[i][2], sf[i][3]));
        #pragma unroll
        for (int off = 1; off < 8; off <<= 1)
            #pragma unroll
            for (int i = 0; i < 8; i++)
                mx8[i] = fmaxf(mx8[i], __shfl_xor_sync(0xFFFFFFFFu, mx8[i], off));

        float cf[8];
        #pragma unroll
        for (int i = 0; i < 8; i++) {
            const float mn = fmaxf(m_[i], mx8[i]);
            cf[i] = __expf(m_[i] - mn);
            m_[i] = mn;
        }

        float ls[8];
        #pragma unroll
        for (int i = 0; i < 8; i++) {
            sf[i][0] = __expf(sf[i][0] - m_[i]);
            sf[i][1] = __expf(sf[i][1] - m_[i]);
            sf[i][2] = __expf(sf[i][2] - m_[i]);
            sf[i][3] = __expf(sf[i][3] - m_[i]);
            ls[i] = (sf[i][0] + sf[i][1]) + (sf[i][2] + sf[i][3]);
        }
        #pragma unroll
        for (int off = 1; off < 8; off <<= 1)
            #pragma unroll
            for (int i = 0; i < 8; i++)
                ls[i] += __shfl_xor_sync(0xFFFFFFFFu, ls[i], off);
        #pragma unroll
        for (int i = 0; i < 8; i++) l_[i] = l_[i]*cf[i] + ls[i];

        Cs[qg*8 + kg] = cf[kg];    // lanes hold identical cf[]; t-contiguous

        // ---- store P swizzled (conflict-free u64 stores):
        //      col = q ^ (kg<<1) ^ ((kg&4)<<2)   [j>>2 == kg, j>>4 == kg>>2]
        {
            const int xsw = (kg << 1) ^ ((kg & 4) << 2);
            #pragma unroll
            for (int k = 0; k < 4; k++) {
                const int j = kg*4 + k;
                #pragma unroll
                for (int p = 0; p < 4; p++) {
                    const int col = (qg*8 + 2*p) ^ xsw;
                    *(u64*)&Ps[j*128 + col] = pack2(sf[2*p][k], sf[2*p+1][k]);
                }
            }
        }
        __syncthreads();   // Ps, Cs ready

        // ---- PV: 8q x 8d per thread, accumulate in regs ----
        #pragma unroll
        for (int qi = 0; qi < 8; qi++) {
            const float cv = Cs[qg*8 + qi];
            const u64 c2 = pack2(cv, cv);
            #pragma unroll
            for (int dp = 0; dp < 4; dp++) o2[qi][dp] = mul2(o2[qi][dp], c2);
        }
        #pragma unroll 4
        for (int j = 0; j < 32; j++) {
            const int Xj = (j >> 2) << 1;                  // 0,2,...,14
            const int gbase = ((qg*8) ^ (Xj & 12)) ^ ((j >> 4) << 4);
            const float4 fa = *(const float4*)&Ps[j*128 + gbase];
            const float4 fb = *(const float4*)&Ps[j*128 + (gbase ^ 4)];
            float pr[8];
            if (Xj & 2) {
                pr[0]=fa.z; pr[1]=fa.w; pr[2]=fa.x; pr[3]=fa.y;
                pr[4]=fb.z; pr[5]=fb.w; pr[6]=fb.x; pr[7]=fb.y;
            } else {
                pr[0]=fa.x; pr[1]=fa.y; pr[2]=fa.z; pr[3]=fa.w;
                pr[4]=fb.x; pr[5]=fb.y; pr[6]=fb.z; pr[7]=fb.w;
            }
            const ulonglong2 va = *(const ulonglong2*)&Vs[j*68 + kg*8];
            const ulonglong2 vb = *(const ulonglong2*)&Vs[j*68 + kg*8 + 4];
            const u64 vp[4] = { va.x, va.y, vb.x, vb.y };
            #pragma unroll
            for (int qi = 0; qi < 8; qi++) {
                const u64 pq = pack2(pr[qi], pr[qi]);
                #pragma unroll
                for (int dp = 0; dp < 4; dp++)
                    o2[qi][dp] = fma2(pq, vp[dp], o2[qi][dp]);
            }
        }
    }

    // ---- epilogue: broadcast 1/l, scale, write [B,S,H*DK] ----
    __syncthreads();
    Cs[qg*8 + kg] = 1.0f / l_[kg];
    __syncthreads();

    const int bb = bh >> 3;
    const int hh = bh & 7;
    #pragma unroll
    for (int qi = 0; qi < 8; qi++) {
        const float inv = Cs[qg*8 + qi];
        const int qo = q0 + qg*8 + qi;
        float* orow = g_attn + ((size_t)(bb*S_ + qo))*D_ + hh*DK_ + kg*8;
        float r[8];
        #pragma unroll
        for (int dp = 0; dp < 4; dp++) unpack2(o2[qi][dp], r[2*dp], r[2*dp+1]);
        float4 t0, t1;
        t0.x = r[0]*inv; t0.y = r[1]*inv; t0.z = r[2]*inv; t0.w = r[3]*inv;
        t1.x = r[4]*inv; t1.y = r[5]*inv; t1.z = r[6]*inv; t1.w = r[7]*inv;
        *(float4*)orow       = t0;
        *(float4*)(orow + 4) = t1;
    }
}

// ---------------------------------------------------------------------------
// Inputs: query, key, value, Wq, bq, Wk, bk, Wv, bv, Wo, bo, mask
// ---------------------------------------------------------------------------
extern "C" void kernel_launch(void* const* d_in, const int* in_sizes, int n_in,
                              void* d_out, int out_size)
{
    const float* query = (const float*)d_in[0];
    const float* key   = (const float*)d_in[1];
    const float* value = (const float*)d_in[2];
    const float* Wq    = (const float*)d_in[3];
    const float* bq    = (const float*)d_in[4];
    const float* Wk    = (const float*)d_in[5];
    const float* bk    = (const float*)d_in[6];
    const float* Wv    = (const float*)d_in[7];
    const float* bv    = (const float*)d_in[8];
    const float* Wo    = (const float*)d_in[9];
    const float* bo    = (const float*)d_in[10];
    float* out = (float*)d_out;

    const dim3 gthr(256);
    const dim3 ggrid(D_/64, M_/64);   // (8, 128)

    gemm_bias_kernel<0><<<ggrid, gthr>>>(query, Wq, bq, nullptr);
    gemm_bias_kernel<1><<<ggrid, gthr>>>(key,   Wk, bk, nullptr);
    gemm_bias_kernel<2><<<ggrid, gthr>>>(value, Wv, bv, nullptr);

    const size_t fsm = FLASH_SMEM_FLOATS * sizeof(float);   // 66560 B
    cudaFuncSetAttribute(flash_kernel,
                         cudaFuncAttributeMaxDynamicSharedMemorySize, (int)fsm);
    const dim3 fgrid(B_*H_, S_/128);  // (16, 32)
    flash_kernel<<<fgrid, 128, fsm>>>();

    gemm_bias_kernel<3><<<ggrid, gthr>>>(nullptr, Wo, bo, out);
}

// round 11
// speedup vs baseline: 1.4335x; 1.2014x over previous
#include <cuda_runtime.h>
#include <cuda_bf16.h>
#include <stdint.h>
#include <math.h>

// MultiHeadedAttention_11562051961106
// B=2, S=4096, D=512, H=8, DK=64. fp32 in/out. Causal (mask input ignored).
//
// Harness targets plain sm_100 (no 'a' features): tcgen05 unavailable.
// Tensor path = mma.sync (HMMA) + ldmatrix, baseline PTX ISA.
//
// Stage 1: q/k/v = x @ W^T + b    -> HMMA bf16-split GEMM (R11)
// Stage 2: causal flash attention -> R6b FFMA2 kernel (unchanged, 1052 us)
// Stage 3: out = attn @ Wo^T + bo -> HMMA bf16-split GEMM (R11)

#define B_  2
#define S_  4096
#define D_  512
#define H_  8
#define DK_ 64
#define M_  (B_*S_)

typedef unsigned long long u64;

// ---- packed f32x2 helpers (flash kernel) -----------------------------------
__device__ __forceinline__ u64 pack2(float lo, float hi) {
    u64 d;
    asm("mov.b64 %0, {%1, %2};" : "=l"(d) : "f"(lo), "f"(hi));
    return d;
}
__device__ __forceinline__ void unpack2(u64 v, float& lo, float& hi) {
    asm("mov.b64 {%0, %1}, %2;" : "=f"(lo), "=f"(hi) : "l"(v));
}
__device__ __forceinline__ u64 fma2(u64 a, u64 b, u64 c) {
    u64 d;
    asm("fma.rn.f32x2 %0, %1, %2, %3;" : "=l"(d) : "l"(a), "l"(b), "l"(c));
    return d;
}
__device__ __forceinline__ u64 mul2(u64 a, u64 b) {
    u64 d;
    asm("mul.rn.f32x2 %0, %1, %2;" : "=l"(d) : "l"(a), "l"(b));
    return d;
}

// Scratch (device globals; no allocation allowed)
__device__ float g_q[(size_t)B_*H_*S_*DK_];
__device__ float g_k[(size_t)B_*H_*S_*DK_];
__device__ float g_v[(size_t)B_*H_*S_*DK_];
__device__ float g_attn[(size_t)M_*D_];

// ---- mma.sync helpers ------------------------------------------------------
__device__ __forceinline__ uint32_t smem_u32(const void* p) {
    uint32_t a;
    asm("{ .reg .u64 t; cvta.to.shared.u64 t, %1; cvt.u32.u64 %0, t; }"
        : "=r"(a) : "l"(p));
    return a;
}
__device__ __forceinline__ void ldsm_x4(uint32_t& r0, uint32_t& r1,
                                        uint32_t& r2, uint32_t& r3, uint32_t addr) {
    asm volatile("ldmatrix.sync.aligned.m8n8.x4.shared.b16 {%0,%1,%2,%3}, [%4];"
                 : "=r"(r0), "=r"(r1), "=r"(r2), "=r"(r3) : "r"(addr));
}
__device__ __forceinline__ void mma_bf16(float& c0, float& c1, float& c2, float& c3,
                                         uint32_t a0, uint32_t a1, uint32_t a2, uint32_t a3,
                                         uint32_t b0, uint32_t b1) {
    asm volatile(
        "mma.sync.aligned.m16n8k16.row.col.f32.bf16.bf16.f32 "
        "{%0,%1,%2,%3}, {%4,%5,%6,%7}, {%8,%9}, {%0,%1,%2,%3};"
        : "+f"(c0), "+f"(c1), "+f"(c2), "+f"(c3)
        : "r"(a0), "r"(a1), "r"(a2), "r"(a3), "r"(b0), "r"(b1));
}
__device__ __forceinline__ uint32_t bf16x2_of(float a, float b) {
    __nv_bfloat162 v = __halves2bfloat162(__float2bfloat16(a), __float2bfloat16(b));
    return *reinterpret_cast<uint32_t*>(&v);
}

// ============================================================================
// HMMA bf16-split GEMM: C = A @ W^T + bias
// A:[M_,512], W:[512,512] row-major (both k-major -> plain ldmatrix, no trans).
// C ~= Ah Wh^T + Ah Wl^T + Al Wh^T   (fp32 accum; rel err ~1e-5)
// Block 256 thr / 8 warps, tile 128m x 64n (warp 32x32), K slabs of 32,
// smem pitch 40 bf16 (80B) -> conflict-free ldmatrix row addressing.
// MODE 0/1/2: out -> g_q/g_k/g_v head-split [B,H,S,DK]; MODE 3: plain [M_,512].
// ============================================================================
#define PITCH 40   // bf16 elements per smem row (80 bytes)

template<int MODE>
__global__ void __launch_bounds__(256) gemm_mma_kernel(
    const float* __restrict__ Ain, const float* __restrict__ W,
    const float* __restrict__ bias, float* __restrict__ outp)
{
    __shared__ __align__(16) __nv_bfloat16 Ah[128*PITCH], Al[128*PITCH];
    __shared__ __align__(16) __nv_bfloat16 Wh[ 64*PITCH], Wl[ 64*PITCH];

    const float* A = (MODE == 3) ? g_attn : Ain;
    const int t    = threadIdx.x;
    const int lane = t & 31;
    const int wid  = t >> 5;
    const int wm   = wid & 3;    // 4 m-warps (32 rows each)
    const int wn   = wid >> 2;   // 2 n-warps (32 cols each)
    const int m0   = blockIdx.y * 128;
    const int n0   = blockIdx.x * 64;

    const uint32_t sAh = smem_u32(Ah), sAl = smem_u32(Al);
    const uint32_t sWh = smem_u32(Wh), sWl = smem_u32(Wl);

    // ldmatrix lane addressing (bytes), k-offset added per use
    // A x4: lanes 0-15 -> rows m..m+15 @k0 ; lanes 16-31 -> same rows @k0+8
    const uint32_t aoff = (uint32_t)((wm*32 + (lane & 15)) * PITCH + (lane >> 4) * 8) * 2;
    // B x4 covering 2 n-tiles: q=lane>>3: row += (q>>1)*8, k += (q&1)*8
    const uint32_t boff = (uint32_t)((wn*32 + ((lane >> 4) ? 8 : 0) + (lane & 7)) * PITCH
                                     + ((lane >> 3) & 1) * 8) * 2;

    float c[2][4][4];
    #pragma unroll
    for (int i = 0; i < 2; i++)
        #pragma unroll
        for (int j = 0; j < 4; j++)
            #pragma unroll
            for (int k = 0; k < 4; k++) c[i][j][k] = 0.f;

    for (int s = 0; s < 16; s++) {
        const int k0s = s * 32;
        __syncthreads();   // previous slab's ldmatrix reads done

        // ---- stage A slab [128 x 32] fp32 -> bf16 hi/lo ----
        #pragma unroll
        for (int p = 0; p < 4; p++) {
            const int idx = t + p * 256;          // 0..1023
            const int row = idx >> 3;
            const int cq  = idx & 7;
            const float4 f = *(const float4*)(A + (size_t)(m0 + row) * D_ + k0s + cq * 4);
            const uint32_t hi01 = bf16x2_of(f.x, f.y);
            const uint32_t hi23 = bf16x2_of(f.z, f.w);
            const float rx = f.x - __uint_as_float(hi01 << 16);
            const float ry = f.y - __uint_as_float(hi01 & 0xFFFF0000u);
            const float rz = f.z - __uint_as_float(hi23 << 16);
            const float rw = f.w - __uint_as_float(hi23 & 0xFFFF0000u);
            *(uint2*)&Ah[row * PITCH + cq * 4] = make_uint2(hi01, hi23);
            *(uint2*)&Al[row * PITCH + cq * 4] = make_uint2(bf16x2_of(rx, ry), bf16x2_of(rz, rw));
        }
        // ---- stage W slab [64 x 32] ----
        #pragma unroll
        for (int p = 0; p < 2; p++) {
            const int idx = t + p * 256;          // 0..511
            const int row = idx >> 3;
            const int cq  = idx & 7;
            const float4 f = *(const float4*)(W + (size_t)(n0 + row) * D_ + k0s + cq * 4);
            const uint32_t hi01 = bf16x2_of(f.x, f.y);
            const uint32_t hi23 = bf16x2_of(f.z, f.w);
            const float rx = f.x - __uint_as_float(hi01 << 16);
            const float ry = f.y - __uint_as_float(hi01 & 0xFFFF0000u);
            const float rz = f.z - __uint_as_float(hi23 << 16);
            const float rw = f.w - __uint_as_float(hi23 & 0xFFFF0000u);
            *(uint2*)&Wh[row * PITCH + cq * 4] = make_uint2(hi01, hi23);
            *(uint2*)&Wl[row * PITCH + cq * 4] = make_uint2(bf16x2_of(rx, ry), bf16x2_of(rz, rw));
        }
        __syncthreads();   // slab ready

        // ---- compute: 2 k-steps x (2m x 4n) x 3 split terms ----
        #pragma unroll
        for (int ks = 0; ks < 2; ks++) {
            const uint32_t kb = (uint32_t)(k0s & 0) + ks * 32;  // byte offset 16 bf16 = 32B

            uint32_t ah[2][4], al[2][4];
            #pragma unroll
            for (int mt = 0; mt < 2; mt++) {
                ldsm_x4(ah[mt][0], ah[mt][1], ah[mt][2], ah[mt][3],
                        sAh + aoff + mt * (16 * PITCH * 2) + kb);
                ldsm_x4(al[mt][0], al[mt][1], al[mt][2], al[mt][3],
                        sAl + aoff + mt * (16 * PITCH * 2) + kb);
            }
            uint32_t wh[4][2], wl[4][2];
            #pragma unroll
            for (int np = 0; np < 2; np++) {
                uint32_t r0, r1, r2, r3;
                ldsm_x4(r0, r1, r2, r3, sWh + boff + np * (16 * PITCH * 2) + kb);
                wh[2*np][0] = r0; wh[2*np][1] = r1; wh[2*np+1][0] = r2; wh[2*np+1][1] = r3;
                ldsm_x4(r0, r1, r2, r3, sWl + boff + np * (16 * PITCH * 2) + kb);
                wl[2*np][0] = r0; wl[2*np][1] = r1; wl[2*np+1][0] = r2; wl[2*np+1][1] = r3;
            }

            #pragma unroll
            for (int mt = 0; mt < 2; mt++)
                #pragma unroll
                for (int nt = 0; nt < 4; nt++) {
                    float* cc = c[mt][nt];
                    mma_bf16(cc[0], cc[1], cc[2], cc[3],
                             ah[mt][0], ah[mt][1], ah[mt][2], ah[mt][3],
                             wh[nt][0], wh[nt][1]);
                    mma_bf16(cc[0], cc[1], cc[2], cc[3],
                             ah[mt][0], ah[mt][1], ah[mt][2], ah[mt][3],
                             wl[nt][0], wl[nt][1]);
                    mma_bf16(cc[0], cc[1], cc[2], cc[3],
                             al[mt][0], al[mt][1], al[mt][2], al[mt][3],
                             wh[nt][0], wh[nt][1]);
                }
        }
    }

    // ---- epilogue: C frag (row g / g+8, cols 2*tig..+1) + bias -> gmem ----
    const int g   = lane >> 2;
    const int tig = lane & 3;
    #pragma unroll
    for (int mt = 0; mt < 2; mt++) {
        #pragma unroll
        for (int nt = 0; nt < 4; nt++) {
            const int n = n0 + wn*32 + nt*8 + tig*2;
            const float b0 = bias[n], b1 = bias[n+1];
            #pragma unroll
            for (int half = 0; half < 2; half++) {
                const int m = m0 + wm*32 + mt*16 + g + half*8;
                const float v0 = c[mt][nt][2*half+0] + b0;
                const float v1 = c[mt][nt][2*half+1] + b1;
                if (MODE < 3) {
                    float* OUT = (MODE == 0) ? g_q : (MODE == 1) ? g_k : g_v;
                    const int bb = m >> 12;
                    const int ss = m & (S_ - 1);
                    const int hh = n >> 6;
                    const int dk = n & (DK_ - 1);
                    float* dst = OUT + ((size_t)((bb*H_ + hh)*S_) + ss)*DK_ + dk;
                    dst[0] = v0; dst[1] = v1;   // pair never crosses a head (n even)
                } else {
                    float* dst = outp + (size_t)m * D_ + n;
                    dst[0] = v0; dst[1] = v1;
                }
            }
        }
    }
}

// ---------------------------------------------------------------------------
// R6b flash attention (unchanged; 1052 us measured).
// ---------------------------------------------------------------------------
#define FLASH_SMEM_FLOATS 16640

__global__ void __launch_bounds__(128, 2) flash_kernel()
{
    extern __shared__ float sm[];
    float* Qs = sm;            // [64][128]
    float* Ks = sm + 8192;     // [64][32]
    float* Vs = sm + 10240;    // [32][68]
    float* Ps = sm + 12416;    // [32][128]
    float* Cs = sm + 16512;    // [128]

    const int bh = blockIdx.x;
    const int qt = gridDim.y - 1 - blockIdx.y;
    const int q0 = qt * 128;
    const int t  = threadIdx.x;
    const int qg = t >> 3;
    const int kg = t & 7;

    {
        const float4* src = (const float4*)(g_q + ((size_t)bh*S_ + q0 + t)*DK_);
        #pragma unroll
        for (int c = 0; c < 16; c++) {
            const float4 f = src[c];
            Qs[(4*c+0)*128 + t] = f.x*0.125f;
            Qs[(4*c+1)*128 + t] = f.y*0.125f;
            Qs[(4*c+2)*128 + t] = f.z*0.125f;
            Qs[(4*c+3)*128 + t] = f.w*0.125f;
        }
    }

    float m_[8], l_[8];
    #pragma unroll
    for (int i = 0; i < 8; i++) { m_[i] = -1e30f; l_[i] = 0.f; }

    u64 o2[8][4];
    #pragma unroll
    for (int i = 0; i < 8; i++)
        #pragma unroll
        for (int j = 0; j < 4; j++) o2[i][j] = 0ull;

    const float* kbase = g_k + (size_t)bh*S_*DK_;
    const float* vbase = g_v + (size_t)bh*S_*DK_;
    const int jl = t & 31;
    const int dh = t >> 5;
    const int kend = q0 + 128;

    for (int j0 = 0; j0 < kend; j0 += 32) {
        __syncthreads();

        {
            const float4* krow = (const float4*)(kbase + (size_t)(j0 + jl)*DK_ + dh*16);
            const float4* vrow = (const float4*)(vbase + (size_t)(j0 + jl)*DK_ + dh*16);
            #pragma unroll
            for (int c = 0; c < 4; c++) {
                const float4 f = krow[c];
                const int d = dh*16 + 4*c;
                Ks[(d+0)*32 + jl] = f.x;
                Ks[(d+1)*32 + jl] = f.y;
                Ks[(d+2)*32 + jl] = f.z;
                Ks[(d+3)*32 + jl] = f.w;
                *(float4*)&Vs[jl*68 + d] = vrow[c];
            }
        }
        __syncthreads();

        u64 acc[4][4];
        #pragma unroll
        for (int p = 0; p < 4; p++)
            #pragma unroll
            for (int k = 0; k < 4; k++) acc[p][k] = 0ull;

        #pragma unroll 8
        for (int d = 0; d < DK_; d++) {
            const ulonglong2 qa = *(const ulonglong2*)&Qs[d*128 + qg*8];
            const ulonglong2 qb = *(const ulonglong2*)&Qs[d*128 + qg*8 + 4];
            const float4 kv = *(const float4*)&Ks[d*32 + kg*4];
            const u64 qp[4] = { qa.x, qa.y, qb.x, qb.y };
            const u64 kd[4] = { pack2(kv.x, kv.x), pack2(kv.y, kv.y),
                                pack2(kv.z, kv.z), pack2(kv.w, kv.w) };
            #pragma unroll
            for (int p = 0; p < 4; p++)
                #pragma unroll
                for (int k = 0; k < 4; k++)
                    acc[p][k] = fma2(qp[p], kd[k], acc[p][k]);
        }

        float sf[8][4];
        #pragma unroll
        for (int p = 0; p < 4; p++)
            #pragma unroll
            for (int k = 0; k < 4; k++)
                unpack2(acc[p][k], sf[2*p][k], sf[2*p+1][k]);

        if (j0 >= q0) {
            const int qb = q0 + qg*8;
            const int jb = j0 + kg*4;
            #pragma unroll
            for (int i = 0; i < 8; i++)
                #pragma unroll
                for (int k = 0; k < 4; k++)
                    if (jb + k > qb + i) sf[i][k] = -1e30f;
        }

        float mx8[8];
        #pragma unroll
        for (int i = 0; i < 8; i++)
            mx8[i] = fmaxf(fmaxf(sf[i][0], sf[i][1]), fmaxf(sf[i][2], sf[i][3]));
        #pragma unroll
        for (int off = 1; off < 8; off <<= 1)
            #pragma unroll
            for (int i = 0; i < 8; i++)
                mx8[i] = fmaxf(mx8[i], __shfl_xor_sync(0xFFFFFFFFu, mx8[i], off));

        float cf[8];
        #pragma unroll
        for (int i = 0; i < 8; i++) {
            const float mn = fmaxf(m_[i], mx8[i]);
            cf[i] = __expf(m_[i] - mn);
            m_[i] = mn;
        }

        float ls[8];
        #pragma unroll
        for (int i = 0; i < 8; i++) {
            sf[i][0] = __expf(sf[i][0] - m_[i]);
            sf[i][1] = __expf(sf[i][1] - m_[i]);
            sf[i][2] = __expf(sf[i][2] - m_[i]);
            sf[i][3] = __expf(sf[i][3] - m_[i]);
            ls[i] = (sf[i][0] + sf[i][1]) + (sf[i][2] + sf[i][3]);
        }
        #pragma unroll
        for (int off = 1; off < 8; off <<= 1)
            #pragma unroll
            for (int i = 0; i < 8; i++)
                ls[i] += __shfl_xor_sync(0xFFFFFFFFu, ls[i], off);
        #pragma unroll
        for (int i = 0; i < 8; i++) l_[i] = l_[i]*cf[i] + ls[i];

        Cs[qg*8 + kg] = cf[kg];

        {
            const int xsw = (kg << 1) ^ ((kg & 4) << 2);
            #pragma unroll
            for (int k = 0; k < 4; k++) {
                const int j = kg*4 + k;
                #pragma unroll
                for (int p = 0; p < 4; p++) {
                    const int col = (qg*8 + 2*p) ^ xsw;
                    *(u64*)&Ps[j*128 + col] = pack2(sf[2*p][k], sf[2*p+1][k]);
                }
            }
        }
        __syncthreads();

        #pragma unroll
        for (int qi = 0; qi < 8; qi++) {
            const float cv = Cs[qg*8 + qi];
            const u64 c2 = pack2(cv, cv);
            #pragma unroll
            for (int dp = 0; dp < 4; dp++) o2[qi][dp] = mul2(o2[qi][dp], c2);
        }
        #pragma unroll 4
        for (int j = 0; j < 32; j++) {
            const int Xj = (j >> 2) << 1;
            const int gbase = ((qg*8) ^ (Xj & 12)) ^ ((j >> 4) << 4);
            const float4 fa = *(const float4*)&Ps[j*128 + gbase];
            const float4 fb = *(const float4*)&Ps[j*128 + (gbase ^ 4)];
            float pr[8];
            if (Xj & 2) {
                pr[0]=fa.z; pr[1]=fa.w; pr[2]=fa.x; pr[3]=fa.y;
                pr[4]=fb.z; pr[5]=fb.w; pr[6]=fb.x; pr[7]=fb.y;
            } else {
                pr[0]=fa.x; pr[1]=fa.y; pr[2]=fa.z; pr[3]=fa.w;
                pr[4]=fb.x; pr[5]=fb.y; pr[6]=fb.z; pr[7]=fb.w;
            }
            const ulonglong2 va = *(const ulonglong2*)&Vs[j*68 + kg*8];
            const ulonglong2 vb = *(const ulonglong2*)&Vs[j*68 + kg*8 + 4];
            const u64 vp[4] = { va.x, va.y, vb.x, vb.y };
            #pragma unroll
            for (int qi = 0; qi < 8; qi++) {
                const u64 pq = pack2(pr[qi], pr[qi]);
                #pragma unroll
                for (int dp = 0; dp < 4; dp++)
                    o2[qi][dp] = fma2(pq, vp[dp], o2[qi][dp]);
            }
        }
    }

    __syncthreads();
    Cs[qg*8 + kg] = 1.0f / l_[kg];
    __syncthreads();

    const int bb = bh >> 3;
    const int hh = bh & 7;
    #pragma unroll
    for (int qi = 0; qi < 8; qi++) {
        const float inv = Cs[qg*8 + qi];
        const int qo = q0 + qg*8 + qi;
        float* orow = g_attn + ((size_t)(bb*S_ + qo))*D_ + hh*DK_ + kg*8;
        float r[8];
        #pragma unroll
        for (int dp = 0; dp < 4; dp++) unpack2(o2[qi][dp], r[2*dp], r[2*dp+1]);
        float4 t0, t1;
        t0.x = r[0]*inv; t0.y = r[1]*inv; t0.z = r[2]*inv; t0.w = r[3]*inv;
        t1.x = r[4]*inv; t1.y = r[5]*inv; t1.z = r[6]*inv; t1.w = r[7]*inv;
        *(float4*)orow       = t0;
        *(float4*)(orow + 4) = t1;
    }
}

// ---------------------------------------------------------------------------
// Inputs: query, key, value, Wq, bq, Wk, bk, Wv, bv, Wo, bo, mask
// ---------------------------------------------------------------------------
extern "C" void kernel_launch(void* const* d_in, const int* in_sizes, int n_in,
                              void* d_out, int out_size)
{
    const float* query = (const float*)d_in[0];
    const float* key   = (const float*)d_in[1];
    const float* value = (const float*)d_in[2];
    const float* Wq    = (const float*)d_in[3];
    const float* bq    = (const float*)d_in[4];
    const float* Wk    = (const float*)d_in[5];
    const float* bk    = (const float*)d_in[6];
    const float* Wv    = (const float*)d_in[7];
    const float* bv    = (const float*)d_in[8];
    const float* Wo    = (const float*)d_in[9];
    const float* bo    = (const float*)d_in[10];
    float* out = (float*)d_out;

    const dim3 ggrid(D_/64, M_/128);   // (8, 64)
    gemm_mma_kernel<0><<<ggrid, 256>>>(query, Wq, bq, nullptr);
    gemm_mma_kernel<1><<<ggrid, 256>>>(key,   Wk, bk, nullptr);
    gemm_mma_kernel<2><<<ggrid, 256>>>(value, Wv, bv, nullptr);

    const size_t fsm = FLASH_SMEM_FLOATS * sizeof(float);   // 66560 B
    cudaFuncSetAttribute(flash_kernel,
                         cudaFuncAttributeMaxDynamicSharedMemorySize, (int)fsm);
    const dim3 fgrid(B_*H_, S_/128);  // (16, 32)
    flash_kernel<<<fgrid, 128, fsm>>>();

    gemm_mma_kernel<3><<<ggrid, 256>>>(nullptr, Wo, bo, out);
}

// round 12
// speedup vs baseline: 3.1256x; 2.1804x over previous
#include <cuda_runtime.h>
#include <cuda_bf16.h>
#include <stdint.h>
#include <math.h>

// MultiHeadedAttention_11562051961106
// B=2, S=4096, D=512, H=8, DK=64. fp32 in/out. Causal (mask input ignored).
//
// sm_100 baseline ISA (no tcgen05). Tensor path = mma.sync bf16 + ldmatrix.
//
// Stage 1: q/k/v proj -> HMMA split-bf16 GEMM, epilogue writes hi/lo bf16
//          (Q pre-scaled by 1/8) in [B,H,S,DK] layout.
// Stage 2: flash attention, FA2-style HMMA: QK and PV both 3-term split-bf16,
//          softmax + online rescale entirely in fragment registers.
// Stage 3: out = attn @ Wo^T + bo -> HMMA split-bf16 GEMM (fp32 out).

#define B_  2
#define S_  4096
#define D_  512
#define H_  8
#define DK_ 64
#define M_  (B_*S_)

// Scratch (device globals; no allocation allowed)
__device__ __nv_bfloat16 g_qh[(size_t)B_*H_*S_*DK_];
__device__ __nv_bfloat16 g_ql[(size_t)B_*H_*S_*DK_];
__device__ __nv_bfloat16 g_kh[(size_t)B_*H_*S_*DK_];
__device__ __nv_bfloat16 g_kl[(size_t)B_*H_*S_*DK_];
__device__ __nv_bfloat16 g_vh[(size_t)B_*H_*S_*DK_];
__device__ __nv_bfloat16 g_vl[(size_t)B_*H_*S_*DK_];
__device__ float g_attn[(size_t)M_*D_];

// ---- mma.sync helpers (validated R11) --------------------------------------
__device__ __forceinline__ uint32_t smem_u32(const void* p) {
    uint32_t a;
    asm("{ .reg .u64 t; cvta.to.shared.u64 t, %1; cvt.u32.u64 %0, t; }"
        : "=r"(a) : "l"(p));
    return a;
}
__device__ __forceinline__ void ldsm_x4(uint32_t& r0, uint32_t& r1,
                                        uint32_t& r2, uint32_t& r3, uint32_t addr) {
    asm volatile("ldmatrix.sync.aligned.m8n8.x4.shared.b16 {%0,%1,%2,%3}, [%4];"
                 : "=r"(r0), "=r"(r1), "=r"(r2), "=r"(r3) : "r"(addr));
}
__device__ __forceinline__ void ldsm_x4_t(uint32_t& r0, uint32_t& r1,
                                          uint32_t& r2, uint32_t& r3, uint32_t addr) {
    asm volatile("ldmatrix.sync.aligned.m8n8.x4.trans.shared.b16 {%0,%1,%2,%3}, [%4];"
                 : "=r"(r0), "=r"(r1), "=r"(r2), "=r"(r3) : "r"(addr));
}
__device__ __forceinline__ void mma_bf16(float& c0, float& c1, float& c2, float& c3,
                                         uint32_t a0, uint32_t a1, uint32_t a2, uint32_t a3,
                                         uint32_t b0, uint32_t b1) {
    asm volatile(
        "mma.sync.aligned.m16n8k16.row.col.f32.bf16.bf16.f32 "
        "{%0,%1,%2,%3}, {%4,%5,%6,%7}, {%8,%9}, {%0,%1,%2,%3};"
        : "+f"(c0), "+f"(c1), "+f"(c2), "+f"(c3)
        : "r"(a0), "r"(a1), "r"(a2), "r"(a3), "r"(b0), "r"(b1));
}
__device__ __forceinline__ uint32_t bf16x2_of(float a, float b) {
    __nv_bfloat162 v = __halves2bfloat162(__float2bfloat16(a), __float2bfloat16(b));
    return *reinterpret_cast<uint32_t*>(&v);
}
// split (a,b) into hi bf16x2 + residual bf16x2
__device__ __forceinline__ void split_pack(float a, float b, uint32_t& hi, uint32_t& lo) {
    const __nv_bfloat16 ha = __float2bfloat16(a), hb = __float2bfloat16(b);
    const float ra = a - __bfloat162float(ha);
    const float rb = b - __bfloat162float(hb);
    const __nv_bfloat162 Hv = __halves2bfloat162(ha, hb);
    hi = *reinterpret_cast<const uint32_t*>(&Hv);
    lo = bf16x2_of(ra, rb);
}

// ============================================================================
// HMMA bf16-split GEMM (R11, validated): C = A @ W^T + bias
// MODE 0/1/2: epilogue splits to hi/lo bf16 -> g_{q,k,v}{h,l} (Q scaled 1/8).
// MODE 3: A = g_attn, fp32 out.
// ============================================================================
#define PITCH 40   // bf16 per smem row (80B) for 32-wide slabs

template<int MODE>
__global__ void __launch_bounds__(256) gemm_mma_kernel(
    const float* __restrict__ Ain, const float* __restrict__ W,
    const float* __restrict__ bias, float* __restrict__ outp)
{
    __shared__ __align__(16) __nv_bfloat16 Ah[128*PITCH], Al[128*PITCH];
    __shared__ __align__(16) __nv_bfloat16 Wh[ 64*PITCH], Wl[ 64*PITCH];

    const float* A = (MODE == 3) ? g_attn : Ain;
    const int t    = threadIdx.x;
    const int lane = t & 31;
    const int wid  = t >> 5;
    const int wm   = wid & 3;
    const int wn   = wid >> 2;
    const int m0   = blockIdx.y * 128;
    const int n0   = blockIdx.x * 64;

    const uint32_t sAh = smem_u32(Ah), sAl = smem_u32(Al);
    const uint32_t sWh = smem_u32(Wh), sWl = smem_u32(Wl);

    const uint32_t aoff = (uint32_t)((wm*32 + (lane & 15)) * PITCH + (lane >> 4) * 8) * 2;
    const uint32_t boff = (uint32_t)((wn*32 + ((lane >> 4) ? 8 : 0) + (lane & 7)) * PITCH
                                     + ((lane >> 3) & 1) * 8) * 2;

    float c[2][4][4];
    #pragma unroll
    for (int i = 0; i < 2; i++)
        #pragma unroll
        for (int j = 0; j < 4; j++)
            #pragma unroll
            for (int k = 0; k < 4; k++) c[i][j][k] = 0.f;

    for (int s = 0; s < 16; s++) {
        const int k0s = s * 32;
        __syncthreads();

        #pragma unroll
        for (int p = 0; p < 4; p++) {
            const int idx = t + p * 256;
            const int row = idx >> 3;
            const int cq  = idx & 7;
            const float4 f = *(const float4*)(A + (size_t)(m0 + row) * D_ + k0s + cq * 4);
            uint32_t h01, l01, h23, l23;
            split_pack(f.x, f.y, h01, l01);
            split_pack(f.z, f.w, h23, l23);
            *(uint2*)&Ah[row * PITCH + cq * 4] = make_uint2(h01, h23);
            *(uint2*)&Al[row * PITCH + cq * 4] = make_uint2(l01, l23);
        }
        #pragma unroll
        for (int p = 0; p < 2; p++) {
            const int idx = t + p * 256;
            const int row = idx >> 3;
            const int cq  = idx & 7;
            const float4 f = *(const float4*)(W + (size_t)(n0 + row) * D_ + k0s + cq * 4);
            uint32_t h01, l01, h23, l23;
            split_pack(f.x, f.y, h01, l01);
            split_pack(f.z, f.w, h23, l23);
            *(uint2*)&Wh[row * PITCH + cq * 4] = make_uint2(h01, h23);
            *(uint2*)&Wl[row * PITCH + cq * 4] = make_uint2(l01, l23);
        }
        __syncthreads();

        #pragma unroll
        for (int ks = 0; ks < 2; ks++) {
            const uint32_t kb = ks * 32;
            uint32_t ah[2][4], al[2][4];
            #pragma unroll
            for (int mt = 0; mt < 2; mt++) {
                ldsm_x4(ah[mt][0], ah[mt][1], ah[mt][2], ah[mt][3],
                        sAh + aoff + mt * (16 * PITCH * 2) + kb);
                ldsm_x4(al[mt][0], al[mt][1], al[mt][2], al[mt][3],
                        sAl + aoff + mt * (16 * PITCH * 2) + kb);
            }
            uint32_t wh[4][2], wl[4][2];
            #pragma unroll
            for (int np = 0; np < 2; np++) {
                uint32_t r0, r1, r2, r3;
                ldsm_x4(r0, r1, r2, r3, sWh + boff + np * (16 * PITCH * 2) + kb);
                wh[2*np][0] = r0; wh[2*np][1] = r1; wh[2*np+1][0] = r2; wh[2*np+1][1] = r3;
                ldsm_x4(r0, r1, r2, r3, sWl + boff + np * (16 * PITCH * 2) + kb);
                wl[2*np][0] = r0; wl[2*np][1] = r1; wl[2*np+1][0] = r2; wl[2*np+1][1] = r3;
            }
            #pragma unroll
            for (int mt = 0; mt < 2; mt++)
                #pragma unroll
                for (int nt = 0; nt < 4; nt++) {
                    float* cc = c[mt][nt];
                    mma_bf16(cc[0], cc[1], cc[2], cc[3],
                             ah[mt][0], ah[mt][1], ah[mt][2], ah[mt][3],
                             wh[nt][0], wh[nt][1]);
                    mma_bf16(cc[0], cc[1], cc[2], cc[3],
                             ah[mt][0], ah[mt][1], ah[mt][2], ah[mt][3],
                             wl[nt][0], wl[nt][1]);
                    mma_bf16(cc[0], cc[1], cc[2], cc[3],
                             al[mt][0], al[mt][1], al[mt][2], al[mt][3],
                             wh[nt][0], wh[nt][1]);
                }
        }
    }

    const int g   = lane >> 2;
    const int tig = lane & 3;
    const float sc = (MODE == 0) ? 0.125f : 1.0f;
    #pragma unroll
    for (int mt = 0; mt < 2; mt++) {
        #pragma unroll
        for (int nt = 0; nt < 4; nt++) {
            const int n = n0 + wn*32 + nt*8 + tig*2;
            const float b0 = bias[n], b1 = bias[n+1];
            #pragma unroll
            for (int half = 0; half < 2; half++) {
                const int m = m0 + wm*32 + mt*16 + g + half*8;
                const float v0 = (c[mt][nt][2*half+0] + b0) * sc;
                const float v1 = (c[mt][nt][2*half+1] + b1) * sc;
                if (MODE < 3) {
                    __nv_bfloat16 *OH, *OL;
                    if      (MODE == 0) { OH = g_qh; OL = g_ql; }
                    else if (MODE == 1) { OH = g_kh; OL = g_kl; }
                    else                { OH = g_vh; OL = g_vl; }
                    const int bb = m >> 12;
                    const int ss = m & (S_ - 1);
                    const int hh = n >> 6;
                    const int dk = n & (DK_ - 1);
                    const size_t idx = ((size_t)((bb*H_ + hh)*S_) + ss)*DK_ + dk;
                    uint32_t hi, lo;
                    split_pack(v0, v1, hi, lo);
                    *(uint32_t*)&OH[idx] = hi;
                    *(uint32_t*)&OL[idx] = lo;
                } else {
                    float* dst = outp + (size_t)m * D_ + n;
                    dst[0] = v0; dst[1] = v1;
                }
            }
        }
    }
}

// ============================================================================
// R12 HMMA flash attention. Grid (B*H, S/128), block 128 (4 warps x 32 q rows).
// Key tiles of 32. All operands pre-split bf16 hi/lo (from projection epilogue).
// QK and PV: 3-term split mma.sync. Softmax + rescale in fragment registers.
// SMEM (55296 B): Qh/Ql [128][72], Kh/Kl/Vh/Vl [32][72] bf16.
// ============================================================================
#define PQ 72
#define PK 72
#define FLASH_SMEM_BYTES ((2*128*PQ + 4*32*PK) * 2)   // 55296

__global__ void __launch_bounds__(128, 2) flash_mma_kernel()
{
    extern __shared__ __nv_bfloat16 smf[];
    __nv_bfloat16* Qh = smf;
    __nv_bfloat16* Ql = smf + 128*PQ;
    __nv_bfloat16* Kh = smf + 2*128*PQ;
    __nv_bfloat16* Kl = Kh + 32*PK;
    __nv_bfloat16* Vh = Kl + 32*PK;
    __nv_bfloat16* Vl = Vh + 32*PK;

    const uint32_t sQh = smem_u32(Qh), sQl = smem_u32(Ql);
    const uint32_t sKh = smem_u32(Kh), sKl = smem_u32(Kl);
    const uint32_t sVh = smem_u32(Vh), sVl = smem_u32(Vl);

    const int bh = blockIdx.x;
    const int qt = gridDim.y - 1 - blockIdx.y;     // heavy-first
    const int q0 = qt * 128;
    const int t  = threadIdx.x;
    const int lane = t & 31;
    const int w    = t >> 5;
    const int g    = lane >> 2;
    const int tig  = lane & 3;
    const int wbase = q0 + w*32;

    // ---- stage Q hi/lo (once): row t ----
    {
        const size_t qi = ((size_t)bh*S_ + q0 + t) * DK_;
        const uint4* srch = (const uint4*)&g_qh[qi];
        const uint4* srcl = (const uint4*)&g_ql[qi];
        #pragma unroll
        for (int c = 0; c < 8; c++) {
            *(uint4*)&Qh[t*PQ + c*8] = srch[c];
            *(uint4*)&Ql[t*PQ + c*8] = srcl[c];
        }
    }

    // ldmatrix lane addresses (bytes)
    const uint32_t aoffQ = (uint32_t)((w*32 + (lane & 15)) * PQ + (lane >> 4) * 8) * 2;
    const uint32_t boffK = (uint32_t)((((lane >> 4) ? 8 : 0) + (lane & 7)) * PK
                                      + ((lane >> 3) & 1) * 8) * 2;
    const uint32_t voffV = (uint32_t)(((((lane >> 3) & 1) * 8) + (lane & 7)) * PK
                                      + (lane >> 4) * 8) * 2;

    float m_[2][2], l_[2][2];
    #pragma unroll
    for (int i = 0; i < 2; i++)
        #pragma unroll
        for (int j = 0; j < 2; j++) { m_[i][j] = -1e30f; l_[i][j] = 0.f; }

    float o[2][8][4];
    #pragma unroll
    for (int i = 0; i < 2; i++)
        #pragma unroll
        for (int j = 0; j < 8; j++)
            #pragma unroll
            for (int k = 0; k < 4; k++) o[i][j][k] = 0.f;

    const int r_st  = t >> 2;     // staging: key row 0..31
    const int qd_st = t & 3;      // staging: 16-elem quarter
    const int kend  = q0 + 128;

    for (int j0 = 0; j0 < kend; j0 += 32) {
        __syncthreads();   // prior tile's ldmatrix reads done

        // ---- stage K/V hi/lo tiles ----
        {
            const size_t gbase = ((size_t)bh*S_ + j0 + r_st) * DK_ + qd_st * 16;
            #pragma unroll
            for (int i = 0; i < 2; i++) {
                const int so = r_st*PK + qd_st*16 + i*8;
                *(uint4*)&Kh[so] = *(const uint4*)&g_kh[gbase + i*8];
                *(uint4*)&Kl[so] = *(const uint4*)&g_kl[gbase + i*8];
                *(uint4*)&Vh[so] = *(const uint4*)&g_vh[gbase + i*8];
                *(uint4*)&Vl[so] = *(const uint4*)&g_vl[gbase + i*8];
            }
        }
        __syncthreads();

        const bool active = (j0 <= wbase);
        if (active) {
            // ---- QK: S[32q x 32k] per warp, split 3-term ----
            float c[2][4][4];
            #pragma unroll
            for (int i = 0; i < 2; i++)
                #pragma unroll
                for (int j = 0; j < 4; j++)
                    #pragma unroll
                    for (int k = 0; k < 4; k++) c[i][j][k] = 0.f;

            #pragma unroll
            for (int ks = 0; ks < 4; ks++) {
                const uint32_t kb = ks * 32;
                uint32_t ah[2][4], al[2][4];
                #pragma unroll
                for (int mt = 0; mt < 2; mt++) {
                    ldsm_x4(ah[mt][0], ah[mt][1], ah[mt][2], ah[mt][3],
                            sQh + aoffQ + mt*(16*PQ*2) + kb);
                    ldsm_x4(al[mt][0], al[mt][1], al[mt][2], al[mt][3],
                            sQl + aoffQ + mt*(16*PQ*2) + kb);
                }
                uint32_t kh[4][2], kl[4][2];
                #pragma unroll
                for (int np = 0; np < 2; np++) {
                    uint32_t r0, r1, r2, r3;
                    ldsm_x4(r0, r1, r2, r3, sKh + boffK + np*(16*PK*2) + kb);
                    kh[2*np][0] = r0; kh[2*np][1] = r1; kh[2*np+1][0] = r2; kh[2*np+1][1] = r3;
                    ldsm_x4(r0, r1, r2, r3, sKl + boffK + np*(16*PK*2) + kb);
                    kl[2*np][0] = r0; kl[2*np][1] = r1; kl[2*np+1][0] = r2; kl[2*np+1][1] = r3;
                }
                #pragma unroll
                for (int mt = 0; mt < 2; mt++)
                    #pragma unroll
                    for (int nt = 0; nt < 4; nt++) {
                        float* cc = c[mt][nt];
                        mma_bf16(cc[0], cc[1], cc[2], cc[3],
                                 ah[mt][0], ah[mt][1], ah[mt][2], ah[mt][3],
                                 kh[nt][0], kh[nt][1]);
                        mma_bf16(cc[0], cc[1], cc[2], cc[3],
                                 ah[mt][0], ah[mt][1], ah[mt][2], ah[mt][3],
                                 kl[nt][0], kl[nt][1]);
                        mma_bf16(cc[0], cc[1], cc[2], cc[3],
                                 al[mt][0], al[mt][1], al[mt][2], al[mt][3],
                                 kh[nt][0], kh[nt][1]);
                    }
            }

            // ---- causal mask (only diagonal tile: j0 == wbase) ----
            if (j0 == wbase) {
                #pragma unroll
                for (int mt = 0; mt < 2; mt++)
                    #pragma unroll
                    for (int nt = 0; nt < 4; nt++)
                        #pragma unroll
                        for (int h = 0; h < 2; h++) {
                            const int row = mt*16 + g + h*8;
                            const int col = nt*8 + 2*tig;
                            if (col     > row) c[mt][nt][2*h+0] = -1e30f;
                            if (col + 1 > row) c[mt][nt][2*h+1] = -1e30f;
                        }
            }

            // ---- softmax in fragment registers ----
            float cf[2][2];
            #pragma unroll
            for (int mt = 0; mt < 2; mt++)
                #pragma unroll
                for (int h = 0; h < 2; h++) {
                    float r = -1e30f;
                    #pragma unroll
                    for (int nt = 0; nt < 4; nt++)
                        r = fmaxf(r, fmaxf(c[mt][nt][2*h], c[mt][nt][2*h+1]));
                    r = fmaxf(r, __shfl_xor_sync(0xFFFFFFFFu, r, 1));
                    r = fmaxf(r, __shfl_xor_sync(0xFFFFFFFFu, r, 2));
                    const float mn = fmaxf(m_[mt][h], r);
                    cf[mt][h] = __expf(m_[mt][h] - mn);
                    m_[mt][h] = mn;
                    float rs = 0.f;
                    #pragma unroll
                    for (int nt = 0; nt < 4; nt++) {
                        const float p0 = __expf(c[mt][nt][2*h+0] - mn);
                        const float p1 = __expf(c[mt][nt][2*h+1] - mn);
                        c[mt][nt][2*h+0] = p0;
                        c[mt][nt][2*h+1] = p1;
                        rs += p0 + p1;
                    }
                    rs += __shfl_xor_sync(0xFFFFFFFFu, rs, 1);
                    rs += __shfl_xor_sync(0xFFFFFFFFu, rs, 2);
                    l_[mt][h] = l_[mt][h] * cf[mt][h] + rs;
                }

            // ---- build P fragments (hi + residual) directly in regs ----
            uint32_t pa[2][2][4], pl[2][2][4];
            #pragma unroll
            for (int mt = 0; mt < 2; mt++)
                #pragma unroll
                for (int ks2 = 0; ks2 < 2; ks2++) {
                    split_pack(c[mt][2*ks2  ][0], c[mt][2*ks2  ][1], pa[mt][ks2][0], pl[mt][ks2][0]);
                    split_pack(c[mt][2*ks2  ][2], c[mt][2*ks2  ][3], pa[mt][ks2][1], pl[mt][ks2][1]);
                    split_pack(c[mt][2*ks2+1][0], c[mt][2*ks2+1][1], pa[mt][ks2][2], pl[mt][ks2][2]);
                    split_pack(c[mt][2*ks2+1][2], c[mt][2*ks2+1][3], pa[mt][ks2][3], pl[mt][ks2][3]);
                }

            // ---- rescale output accumulators ----
            #pragma unroll
            for (int mt = 0; mt < 2; mt++)
                #pragma unroll
                for (int nt8 = 0; nt8 < 8; nt8++) {
                    o[mt][nt8][0] *= cf[mt][0];
                    o[mt][nt8][1] *= cf[mt][0];
                    o[mt][nt8][2] *= cf[mt][1];
                    o[mt][nt8][3] *= cf[mt][1];
                }

            // ---- PV: O[32q x 64d], V via ldmatrix.trans ----
            #pragma unroll
            for (int ks2 = 0; ks2 < 2; ks2++) {
                uint32_t vh[8][2], vl[8][2];
                #pragma unroll
                for (int np = 0; np < 4; np++) {
                    uint32_t r0, r1, r2, r3;
                    ldsm_x4_t(r0, r1, r2, r3, sVh + voffV + ks2*(16*PK*2) + np*32);
                    vh[2*np][0] = r0; vh[2*np][1] = r1; vh[2*np+1][0] = r2; vh[2*np+1][1] = r3;
                    ldsm_x4_t(r0, r1, r2, r3, sVl + voffV + ks2*(16*PK*2) + np*32);
                    vl[2*np][0] = r0; vl[2*np][1] = r1; vl[2*np+1][0] = r2; vl[2*np+1][1] = r3;
                }
                #pragma unroll
                for (int mt = 0; mt < 2; mt++)
                    #pragma unroll
                    for (int nt8 = 0; nt8 < 8; nt8++) {
                        float* oo = o[mt][nt8];
                        mma_bf16(oo[0], oo[1], oo[2], oo[3],
                                 pa[mt][ks2][0], pa[mt][ks2][1], pa[mt][ks2][2], pa[mt][ks2][3],
                                 vh[nt8][0], vh[nt8][1]);
                        mma_bf16(oo[0], oo[1], oo[2], oo[3],
                                 pa[mt][ks2][0], pa[mt][ks2][1], pa[mt][ks2][2], pa[mt][ks2][3],
                                 vl[nt8][0], vl[nt8][1]);
                        mma_bf16(oo[0], oo[1], oo[2], oo[3],
                                 pl[mt][ks2][0], pl[mt][ks2][1], pl[mt][ks2][2], pl[mt][ks2][3],
                                 vh[nt8][0], vh[nt8][1]);
                    }
            }
        }
    }

    // ---- epilogue: O / l -> g_attn[B,S,H*DK] ----
    const int bb = bh >> 3;
    const int hh = bh & 7;
    float inv[2][2];
    #pragma unroll
    for (int mt = 0; mt < 2; mt++)
        #pragma unroll
        for (int h = 0; h < 2; h++) inv[mt][h] = 1.0f / l_[mt][h];

    #pragma unroll
    for (int mt = 0; mt < 2; mt++)
        #pragma unroll
        for (int nt8 = 0; nt8 < 8; nt8++)
            #pragma unroll
            for (int h = 0; h < 2; h++) {
                const int row = q0 + w*32 + mt*16 + g + h*8;
                float2 v;
                v.x = o[mt][nt8][2*h+0] * inv[mt][h];
                v.y = o[mt][nt8][2*h+1] * inv[mt][h];
                *(float2*)&g_attn[(size_t)(bb*S_ + row)*D_ + hh*DK_ + nt8*8 + 2*tig] = v;
            }
}

// ---------------------------------------------------------------------------
// Inputs: query, key, value, Wq, bq, Wk, bk, Wv, bv, Wo, bo, mask
// ---------------------------------------------------------------------------
extern "C" void kernel_launch(void* const* d_in, const int* in_sizes, int n_in,
                              void* d_out, int out_size)
{
    const float* query = (const float*)d_in[0];
    const float* key   = (const float*)d_in[1];
    const float* value = (const float*)d_in[2];
    const float* Wq    = (const float*)d_in[3];
    const float* bq    = (const float*)d_in[4];
    const float* Wk    = (const float*)d_in[5];
    const float* bk    = (const float*)d_in[6];
    const float* Wv    = (const float*)d_in[7];
    const float* bv    = (const float*)d_in[8];
    const float* Wo    = (const float*)d_in[9];
    const float* bo    = (const float*)d_in[10];
    float* out = (float*)d_out;

    const dim3 ggrid(D_/64, M_/128);   // (8, 64)
    gemm_mma_kernel<0><<<ggrid, 256>>>(query, Wq, bq, nullptr);
    gemm_mma_kernel<1><<<ggrid, 256>>>(key,   Wk, bk, nullptr);
    gemm_mma_kernel<2><<<ggrid, 256>>>(value, Wv, bv, nullptr);

    cudaFuncSetAttribute(flash_mma_kernel,
                         cudaFuncAttributeMaxDynamicSharedMemorySize, FLASH_SMEM_BYTES);
    const dim3 fgrid(B_*H_, S_/128);  // (16, 32)
    flash_mma_kernel<<<fgrid, 128, FLASH_SMEM_BYTES>>>();

    gemm_mma_kernel<3><<<ggrid, 256>>>(nullptr, Wo, bo, out);
}